// round 9
// baseline (speedup 1.0000x reference)
#include <cuda_runtime.h>
#include <cuda_bf16.h>
#include <math.h>
#include <cstdint>

// ---------------- problem constants ----------------
#define NROI 128
#define CCH  256
#define ECH  256
#define M_GEMM (NROI*9)      // 1152
#define K_GEMM (CCH*9)       // 2304
#define N_GEMM ECH           // 256

#define SPLITK 8
#define KSLICE (K_GEMM/SPLITK)   // 288
#define BK     32
#define NSTAGE (KSLICE/BK)       // 9

// packed-bf16 smem layout: row = 16 uint32 (32 bf16), stride 20 (bank-safe)
#define PSTRIDE 20
#define PTILE   (128*PSTRIDE)                 // uint32 per tile
#define GEMM_SMEM_BYTES (2 * 4 * PTILE * 4)   // 81920 bytes

// ---------------- device scratch (no runtime alloc allowed) ----------------
// g_R layout: [n][p][c]  (point-major so roi writes coalesce)
__device__ __align__(256) float g_R[(size_t)NROI * 9 * CCH];               // 1.18 MB
__device__ __align__(256) float g_hpart[(size_t)SPLITK * M_GEMM * N_GEMM]; // 9.4 MB

__device__ __forceinline__ uint32_t bf2pack(float v0, float v1) {
    __nv_bfloat162 t;
    t.x = __float2bfloat16(v0);
    t.y = __float2bfloat16(v1);
    return *reinterpret_cast<uint32_t*>(&t);
}
__device__ __forceinline__ float bfhi(float v) {
    return __bfloat162float(__float2bfloat16(v));
}

__device__ __forceinline__ void mma_bf16(float c[4],
                                         uint32_t a0, uint32_t a1, uint32_t a2, uint32_t a3,
                                         uint32_t b0, uint32_t b1) {
    asm volatile(
        "mma.sync.aligned.m16n8k16.row.col.f32.bf16.bf16.f32 "
        "{%0,%1,%2,%3}, {%4,%5,%6,%7}, {%8,%9}, {%0,%1,%2,%3};"
        : "+f"(c[0]), "+f"(c[1]), "+f"(c[2]), "+f"(c[3])
        : "r"(a0), "r"(a1), "r"(a2), "r"(a3), "r"(b0), "r"(b1));
}

// ---------------------------------------------------------------------------
// K1: ROI-align -> compact R[n][p][c].  grid (NROI, 9) x 256 threads.
// Uniform (y0,x0) per CTA: one aligned float4 per row covers both x-taps
// (plus 2 scalars only when x0%4==3). Mean 2.5 loads/thread vs 4.
// ---------------------------------------------------------------------------
__global__ void __launch_bounds__(256) k_roi(
    const float* __restrict__ fm, const float* __restrict__ boxes,
    const int* __restrict__ batch_idx, const int* __restrict__ level_idx)
{
    const int n = blockIdx.x;
    const int p = blockIdx.y;           // 0..8
    const int c = threadIdx.x;
    const int py = p / 3, px = p - py * 3;

    const int lvl = level_idx[n];
    const int b   = batch_idx[n];
    const float hv     = (float)(128 >> lvl);
    const float scale  = 1.0f / (float)(8 << lvl);

    const float x1 = boxes[n*4+0] * scale;
    const float y1 = boxes[n*4+1] * scale;
    const float x2 = boxes[n*4+2] * scale;
    const float y2 = boxes[n*4+3] * scale;
    const float roi_w = fmaxf(x2 - x1, 1.0f);
    const float roi_h = fmaxf(y2 - y1, 1.0f);

    const float y = y1 + (((float)py + 0.5f) / 3.0f) * roi_h;
    const float x = x1 + (((float)px + 0.5f) / 3.0f) * roi_w;
    const bool valid = (y > -1.0f) && (y < hv) && (x > -1.0f) && (x < hv);

    const float yc = fminf(fmaxf(y, 0.0f), hv - 1.0f);
    const float xc = fminf(fmaxf(x, 0.0f), hv - 1.0f);
    const int y0 = (int)floorf(yc);
    const int x0 = (int)floorf(xc);
    const int hi = (int)(hv - 1.0f);
    const int y1i = min(y0 + 1, hi);
    const float ly = yc - (float)y0;
    const float lx = xc - (float)x0;

    const float* __restrict__ plane =
        fm + ((size_t)(lvl*2 + b) * CCH + c) * 128 * 128;

    const int xa = x0 & ~3;
    const int xr = x0 - xa;             // 0..3, uniform over the CTA
    const float4 t0 = *(const float4*)(plane + y0  * 128 + xa);
    const float4 t1 = *(const float4*)(plane + y1i * 128 + xa);

    float v00, v01, v10, v11;
    if (xr == 0)      { v00 = t0.x; v01 = t0.y; v10 = t1.x; v11 = t1.y; }
    else if (xr == 1) { v00 = t0.y; v01 = t0.z; v10 = t1.y; v11 = t1.z; }
    else if (xr == 2) { v00 = t0.z; v01 = t0.w; v10 = t1.z; v11 = t1.w; }
    else {
        v00 = t0.w; v10 = t1.w;
        // x0+1 may be 1 past the logical row; the read stays inside fm and
        // its weight (lx) is 0 whenever x0 was clamped to the edge.
        v01 = plane[y0  * 128 + x0 + 1];
        v11 = plane[y1i * 128 + x0 + 1];
    }

    float val = (1.0f-ly)*(1.0f-lx)*v00 + (1.0f-ly)*lx*v01
              + ly*(1.0f-lx)*v10 + ly*lx*v11;

    g_R[(size_t)(n * 9 + p) * CCH + c] = valid ? val : 0.0f;
}

// ---------------------------------------------------------------------------
// K2: 3x-BF16 mma.sync GEMM (m16n8k16), fused im2col A-gather, double-buffered.
// grid (9, 2, 8) = 144 CTAs, 256 thr (8 warps 4x2), warp tile 32x64.
// ---------------------------------------------------------------------------
__global__ void __launch_bounds__(256, 1) k_gemm_mma(const float* __restrict__ conv_w)
{
    extern __shared__ uint32_t smu[];   // [2 buf][Ah|Al|Bh|Bl][128*PSTRIDE]

    const int tid  = threadIdx.x;
    const int wid  = tid >> 5;
    const int lane = tid & 31;
    const int warp_m = wid & 3;
    const int warp_n = wid >> 2;

    const int m0 = blockIdx.x * 128;
    const int n0 = blockIdx.y * 128;
    const int k0 = blockIdx.z * KSLICE;

    const int pc   = tid & 15;          // A packed col (constant per thread)
    const int lrow = tid >> 3;          // B gmem row base
    const int lcol = (tid & 7) * 4;     // B gmem k offset (float4)

    float acc[2][8][4];
    #pragma unroll
    for (int i = 0; i < 2; i++)
        #pragma unroll
        for (int j = 0; j < 8; j++)
            #pragma unroll
            for (int q = 0; q < 4; q++) acc[i][j][q] = 0.0f;

    const float* __restrict__ Bbase = conv_w + (size_t)n0 * K_GEMM + k0;

    // A-gather row decode: rows (tid>>4) + i*16, i<8
    int a_n[8], a_py[8], a_px[8];
    #pragma unroll
    for (int i = 0; i < 8; i++) {
        const int row = (tid >> 4) + i * 16;
        const int m = m0 + row;
        const int n = m / 9;
        const int p = m - n * 9;
        a_n[i] = n;
        a_py[i] = p / 3;
        a_px[i] = p - (p / 3) * 3;
    }

    float ra[16];
    float4 rb[4];

    // ---- gather helper (stage kbase) ----
    #define GATHER_A(kbase_)                                                   \
        _Pragma("unroll")                                                      \
        for (int i = 0; i < 8; i++) {                                          \
            _Pragma("unroll")                                                  \
            for (int t = 0; t < 2; t++) {                                      \
                const int k = (kbase_) + pc * 2 + t;                           \
                const int c = k / 9;                                           \
                const int kk = k - c * 9;                                      \
                const int ky = kk / 3, kx = kk - ky * 3;                       \
                const int iy = a_py[i] + ky - 1, ix = a_px[i] + kx - 1;        \
                ra[2*i+t] = ((unsigned)iy < 3u && (unsigned)ix < 3u)           \
                    ? g_R[(size_t)(a_n[i] * 9 + iy * 3 + ix) * CCH + c] : 0.0f;\
            }                                                                  \
        }

    #define STORE_STAGE(bufsel)                                                \
        {                                                                      \
            uint32_t* dAh = smu + (bufsel) * (4 * PTILE);                      \
            uint32_t* dAl = dAh + PTILE;                                       \
            uint32_t* dBh = dAl + PTILE;                                       \
            uint32_t* dBl = dBh + PTILE;                                       \
            _Pragma("unroll")                                                  \
            for (int i = 0; i < 8; i++) {                                      \
                const int row = (tid >> 4) + i * 16;                           \
                const float v0 = ra[2*i], v1 = ra[2*i+1];                      \
                dAh[row * PSTRIDE + pc] = bf2pack(v0, v1);                     \
                dAl[row * PSTRIDE + pc] = bf2pack(v0 - bfhi(v0), v1 - bfhi(v1));\
            }                                                                  \
            _Pragma("unroll")                                                  \
            for (int q = 0; q < 4; q++) {                                      \
                const int row = (tid >> 3) + q * 32;                           \
                const float4 v = rb[q];                                        \
                const int base = row * PSTRIDE + (tid & 7) * 2;                \
                dBh[base]     = bf2pack(v.x, v.y);                             \
                dBh[base + 1] = bf2pack(v.z, v.w);                             \
                dBl[base]     = bf2pack(v.x - bfhi(v.x), v.y - bfhi(v.y));     \
                dBl[base + 1] = bf2pack(v.z - bfhi(v.z), v.w - bfhi(v.w));     \
            }                                                                  \
        }

    // stage 0 prefetch + store
    GATHER_A(k0)
    #pragma unroll
    for (int q = 0; q < 4; q++)
        rb[q] = *(const float4*)(Bbase + (size_t)(lrow + q * 32) * K_GEMM + lcol);
    STORE_STAGE(0)
    __syncthreads();

    for (int s = 0; s < NSTAGE; s++) {
        // issue next-stage gmem loads
        if (s + 1 < NSTAGE) {
            GATHER_A(k0 + (s + 1) * BK)
            #pragma unroll
            for (int q = 0; q < 4; q++)
                rb[q] = *(const float4*)(Bbase + (size_t)(lrow + q * 32) * K_GEMM
                                         + (s + 1) * BK + lcol);
        }

        // compute from buffer s&1
        {
            const uint32_t* sAh = smu + (s & 1) * (4 * PTILE);
            const uint32_t* sAl = sAh + PTILE;
            const uint32_t* sBh = sAl + PTILE;
            const uint32_t* sBl = sBh + PTILE;

            const int rbase = warp_m * 32 + (lane >> 2);
            const int nbase = warp_n * 64 + (lane >> 2);
            #pragma unroll
            for (int kc = 0; kc < 2; kc++) {
                const int kb = kc * 8 + (lane & 3);
                uint32_t ah[2][4], al[2][4];
                #pragma unroll
                for (int i = 0; i < 2; i++) {
                    const int r = rbase + i * 16;
                    ah[i][0] = sAh[r * PSTRIDE + kb];
                    ah[i][1] = sAh[(r + 8) * PSTRIDE + kb];
                    ah[i][2] = sAh[r * PSTRIDE + kb + 4];
                    ah[i][3] = sAh[(r + 8) * PSTRIDE + kb + 4];
                    al[i][0] = sAl[r * PSTRIDE + kb];
                    al[i][1] = sAl[(r + 8) * PSTRIDE + kb];
                    al[i][2] = sAl[r * PSTRIDE + kb + 4];
                    al[i][3] = sAl[(r + 8) * PSTRIDE + kb + 4];
                }
                #pragma unroll
                for (int j = 0; j < 8; j++) {
                    const int nn = nbase + j * 8;
                    const uint32_t bh0 = sBh[nn * PSTRIDE + kb];
                    const uint32_t bh1 = sBh[nn * PSTRIDE + kb + 4];
                    const uint32_t bl0 = sBl[nn * PSTRIDE + kb];
                    const uint32_t bl1 = sBl[nn * PSTRIDE + kb + 4];
                    #pragma unroll
                    for (int i = 0; i < 2; i++) {
                        mma_bf16(acc[i][j], ah[i][0], ah[i][1], ah[i][2], ah[i][3], bh0, bh1);
                        mma_bf16(acc[i][j], ah[i][0], ah[i][1], ah[i][2], ah[i][3], bl0, bl1);
                        mma_bf16(acc[i][j], al[i][0], al[i][1], al[i][2], al[i][3], bh0, bh1);
                    }
                }
            }
        }

        // store next stage into other buffer
        if (s + 1 < NSTAGE) {
            STORE_STAGE((s + 1) & 1)
        }
        __syncthreads();
    }

    float* __restrict__ hp = g_hpart + (size_t)blockIdx.z * ((size_t)M_GEMM * N_GEMM);
    #pragma unroll
    for (int i = 0; i < 2; i++) {
        const int row = m0 + warp_m * 32 + i * 16 + (lane >> 2);
        #pragma unroll
        for (int j = 0; j < 8; j++) {
            const int col = n0 + warp_n * 64 + j * 8 + 2 * (lane & 3);
            *(float2*)(hp + (size_t)row * N_GEMM + col) =
                make_float2(acc[i][j][0], acc[i][j][1]);
            *(float2*)(hp + (size_t)(row + 8) * N_GEMM + col) =
                make_float2(acc[i][j][2], acc[i][j][3]);
        }
    }
}

// ---------------------------------------------------------------------------
// K3: per-roi epilogue with fused split-K reduce. 1024 threads.
// ---------------------------------------------------------------------------
__global__ void __launch_bounds__(1024) k_epilogue(
    const float* __restrict__ boxes,
    const float* __restrict__ gn_scale, const float* __restrict__ gn_bias,
    const float* __restrict__ head_w,   const float* __restrict__ head_b,
    const float* __restrict__ spat_w,   const float* __restrict__ spat_b,
    const float* __restrict__ sym_emb,
    const float* __restrict__ fuse_w,   const float* __restrict__ fuse_b,
    const int*   __restrict__ sym_ids,
    float* __restrict__ out)
{
    const int n   = blockIdx.x;
    const int tid = threadIdx.x;
    const int w   = tid >> 5;
    const int l   = tid & 31;

    __shared__ __align__(16) float hred[9 * 256];
    __shared__ __align__(16) float sbuf[256];
    __shared__ __align__(16) float fbuf[256];
    __shared__ float hobuf[256];

    const int sym = sym_ids[n];

    // ---- Phase 0: split-K reduce (float4, coalesced): 576 float4s ----
    if (tid < 576) {
        const float4* __restrict__ hp4 = (const float4*)g_hpart;
        const size_t stride4 = (size_t)M_GEMM * N_GEMM / 4;
        const size_t base4 = (size_t)(n * 9) * (N_GEMM / 4) + tid;
        float4 s = hp4[base4];
        #pragma unroll
        for (int sp = 1; sp < SPLITK; sp++) {
            const float4 v = hp4[(size_t)sp * stride4 + base4];
            s.x += v.x; s.y += v.y; s.z += v.z; s.w += v.w;
        }
        ((float4*)hred)[tid] = s;
    }
    __syncthreads();

    // ---- Phase 1: GN + relu + spatial mean (threads 0..255; warp == group) ----
    if (tid < 256) {
        const int e = tid;
        float hvp[9];
        #pragma unroll
        for (int p = 0; p < 9; p++)
            hvp[p] = hred[p * 256 + e];

        float lsum = 0.0f;
        #pragma unroll
        for (int p = 0; p < 9; p++) lsum += hvp[p];
        #pragma unroll
        for (int o = 16; o > 0; o >>= 1) lsum += __shfl_xor_sync(0xffffffffu, lsum, o);
        const float mean = lsum * (1.0f / 288.0f);

        float lsq = 0.0f;
        #pragma unroll
        for (int p = 0; p < 9; p++) { float d = hvp[p] - mean; lsq += d * d; }
        #pragma unroll
        for (int o = 16; o > 0; o >>= 1) lsq += __shfl_xor_sync(0xffffffffu, lsq, o);
        const float inv = rsqrtf(lsq * (1.0f / 288.0f) + 1e-5f);

        const float sc = gn_scale[e];
        const float bi = gn_bias[e];
        float acc = 0.0f;
        #pragma unroll
        for (int p = 0; p < 9; p++)
            acc += fmaxf((hvp[p] - mean) * inv * sc + bi, 0.0f);
        sbuf[e] = acc * (1.0f / 9.0f);
    }
    __syncthreads();

    // ---- Phase 2: head GEMV (warp w -> outputs w*8..w*8+7, float4 loads) ----
    {
        const float4 sva = *(const float4*)&sbuf[l * 4];
        const float4 svb = *(const float4*)&sbuf[128 + l * 4];

        float a[8];
        #pragma unroll
        for (int o = 0; o < 8; o++) {
            const float* __restrict__ row = head_w + (size_t)(w * 8 + o) * 256;
            const float4 wa = *(const float4*)(row + l * 4);
            const float4 wb = *(const float4*)(row + 128 + l * 4);
            float t = sva.x * wa.x + sva.y * wa.y + sva.z * wa.z + sva.w * wa.w;
            t = fmaf(svb.x, wb.x, t); t = fmaf(svb.y, wb.y, t);
            t = fmaf(svb.z, wb.z, t); t = fmaf(svb.w, wb.w, t);
            a[o] = t;
        }
        #pragma unroll
        for (int o = 0; o < 8; o++) {
            #pragma unroll
            for (int off = 16; off > 0; off >>= 1)
                a[o] += __shfl_xor_sync(0xffffffffu, a[o], off);
        }
        if (l < 8) {
            const int e = w * 8 + l;
            float v = a[0];
            #pragma unroll
            for (int o = 1; o < 8; o++) v = (l == o) ? a[o] : v;
            hobuf[e] = v + head_b[e];
        }
    }
    __syncthreads();

    // ---- fused vector (threads 0..255) ----
    if (tid < 256) {
        const int e = tid;
        const float ho = fmaxf(hobuf[e], 0.0f);
        const float b0 = boxes[n*4+0], b1 = boxes[n*4+1],
                    b2 = boxes[n*4+2], b3 = boxes[n*4+3];
        float sp = spat_b[e] + b0 * spat_w[e*4+0] + b1 * spat_w[e*4+1]
                             + b2 * spat_w[e*4+2] + b3 * spat_w[e*4+3];
        sp = fmaxf(sp, 0.0f);
        fbuf[e] = ho + sp + sym_emb[sym * 256 + e];
    }
    __syncthreads();

    // ---- Phase 3: fuse GEMV ----
    {
        const float4 fva = *(const float4*)&fbuf[l * 4];
        const float4 fvb = *(const float4*)&fbuf[128 + l * 4];

        float a[8];
        #pragma unroll
        for (int o = 0; o < 8; o++) {
            const float* __restrict__ row =
                fuse_w + ((size_t)sym * 256 + (size_t)(w * 8 + o)) * 256;
            const float4 wa = *(const float4*)(row + l * 4);
            const float4 wb = *(const float4*)(row + 128 + l * 4);
            float t = fva.x * wa.x + fva.y * wa.y + fva.z * wa.z + fva.w * wa.w;
            t = fmaf(fvb.x, wb.x, t); t = fmaf(fvb.y, wb.y, t);
            t = fmaf(fvb.z, wb.z, t); t = fmaf(fvb.w, wb.w, t);
            a[o] = t;
        }
        #pragma unroll
        for (int o = 0; o < 8; o++) {
            #pragma unroll
            for (int off = 16; off > 0; off >>= 1)
                a[o] += __shfl_xor_sync(0xffffffffu, a[o], off);
        }
        if (l < 8) {
            const int e = w * 8 + l;
            float v = a[0];
            #pragma unroll
            for (int o = 1; o < 8; o++) v = (l == o) ? a[o] : v;
            out[(size_t)n * 256 + e] = fmaxf(v + fuse_b[sym * 256 + e], 0.0f);
        }
    }
}

// ---------------------------------------------------------------------------
extern "C" void kernel_launch(void* const* d_in, const int* in_sizes, int n_in,
                              void* d_out, int out_size)
{
    const float* fm        = (const float*)d_in[0];
    const float* boxes     = (const float*)d_in[1];
    const float* conv_w    = (const float*)d_in[2];
    const float* gn_scale  = (const float*)d_in[3];
    const float* gn_bias   = (const float*)d_in[4];
    const float* head_w    = (const float*)d_in[5];
    const float* head_b    = (const float*)d_in[6];
    const float* spat_w    = (const float*)d_in[7];
    const float* spat_b    = (const float*)d_in[8];
    const float* sym_emb   = (const float*)d_in[9];
    const float* fuse_w    = (const float*)d_in[10];
    const float* fuse_b    = (const float*)d_in[11];
    const int*   batch_idx = (const int*)d_in[12];
    const int*   level_idx = (const int*)d_in[13];
    const int*   sym_ids   = (const int*)d_in[14];
    float* out = (float*)d_out;

    cudaFuncSetAttribute(k_gemm_mma,
                         cudaFuncAttributeMaxDynamicSharedMemorySize, GEMM_SMEM_BYTES);

    dim3 g1(NROI, 9);
    k_roi<<<g1, 256>>>(fm, boxes, batch_idx, level_idx);

    dim3 g2(M_GEMM / 128, N_GEMM / 128, SPLITK);   // (9, 2, 8) = 144 CTAs
    k_gemm_mma<<<g2, 256, GEMM_SMEM_BYTES>>>(conv_w);

    k_epilogue<<<NROI, 1024>>>(boxes, gn_scale, gn_bias, head_w, head_b,
                               spat_w, spat_b, sym_emb, fuse_w, fuse_b,
                               sym_ids, out);
}

// round 10
// speedup vs baseline: 1.0634x; 1.0634x over previous
#include <cuda_runtime.h>
#include <cuda_bf16.h>
#include <math.h>
#include <cstdint>

// ---------------- problem constants ----------------
#define NROI 128
#define CCH  256
#define ECH  256
#define M_GEMM (NROI*9)      // 1152
#define K_GEMM (CCH*9)       // 2304
#define N_GEMM ECH           // 256

#define SPLITK 8
#define KSLICE (K_GEMM/SPLITK)   // 288
#define BK     32
#define NSTAGE (KSLICE/BK)       // 9

// packed-bf16 smem layout: row = 16 uint32 (32 bf16), stride 20 (bank-safe)
#define PSTRIDE 20
#define PTILE   (128*PSTRIDE)                 // uint32 per tile
#define GEMM_SMEM_BYTES (2 * 4 * PTILE * 4)   // 81920 bytes

// ---------------- device scratch (no runtime alloc allowed) ----------------
// g_R layout: [n][p][c]  (point-major so roi writes coalesce)
__device__ __align__(256) float g_R[(size_t)NROI * 9 * CCH];               // 1.18 MB
__device__ __align__(256) float g_hpart[(size_t)SPLITK * M_GEMM * N_GEMM]; // 9.4 MB

__device__ __forceinline__ uint32_t bf2pack(float v0, float v1) {
    __nv_bfloat162 t;
    t.x = __float2bfloat16(v0);
    t.y = __float2bfloat16(v1);
    return *reinterpret_cast<uint32_t*>(&t);
}
__device__ __forceinline__ float bfhi(float v) {
    return __bfloat162float(__float2bfloat16(v));
}

__device__ __forceinline__ void mma_bf16(float c[4],
                                         uint32_t a0, uint32_t a1, uint32_t a2, uint32_t a3,
                                         uint32_t b0, uint32_t b1) {
    asm volatile(
        "mma.sync.aligned.m16n8k16.row.col.f32.bf16.bf16.f32 "
        "{%0,%1,%2,%3}, {%4,%5,%6,%7}, {%8,%9}, {%0,%1,%2,%3};"
        : "+f"(c[0]), "+f"(c[1]), "+f"(c[2]), "+f"(c[3])
        : "r"(a0), "r"(a1), "r"(a2), "r"(a3), "r"(b0), "r"(b1));
}

// ---------------------------------------------------------------------------
// K1: ROI-align -> compact R[n][p][c].  grid (NROI, 3) x 256 threads.
// Thread = channel, handles one row (py) of 3 sample points: 6 independent
// float4 loads batched up-front (MLP ~6 vs 2) before any combine arithmetic.
// ---------------------------------------------------------------------------
__global__ void __launch_bounds__(256) k_roi(
    const float* __restrict__ fm, const float* __restrict__ boxes,
    const int* __restrict__ batch_idx, const int* __restrict__ level_idx)
{
    const int n  = blockIdx.x;
    const int py = blockIdx.y;          // 0..2
    const int c  = threadIdx.x;

    const int lvl = level_idx[n];
    const int b   = batch_idx[n];
    const float hv    = (float)(128 >> lvl);
    const float scale = 1.0f / (float)(8 << lvl);

    const float bx1 = boxes[n*4+0] * scale;
    const float by1 = boxes[n*4+1] * scale;
    const float bx2 = boxes[n*4+2] * scale;
    const float by2 = boxes[n*4+3] * scale;
    const float roi_w = fmaxf(bx2 - bx1, 1.0f);
    const float roi_h = fmaxf(by2 - by1, 1.0f);

    const float y = by1 + (((float)py + 0.5f) / 3.0f) * roi_h;
    const bool yok = (y > -1.0f) && (y < hv);
    const float yc = fminf(fmaxf(y, 0.0f), hv - 1.0f);
    const int y0 = (int)floorf(yc);
    const int hi = (int)(hv - 1.0f);
    const int y1i = min(y0 + 1, hi);
    const float ly = yc - (float)y0;

    const float* __restrict__ plane =
        fm + ((size_t)(lvl*2 + b) * CCH + c) * 128 * 128;

    float4 t0[3], t1[3];
    float  e0[3], e1[3];
    float  lxv[3];
    int    xrv[3];
    bool   vld[3];

    // ---- load phase: all taps issued before any combine ----
    #pragma unroll
    for (int px = 0; px < 3; px++) {
        const float x = bx1 + (((float)px + 0.5f) / 3.0f) * roi_w;
        vld[px] = yok && (x > -1.0f) && (x < hv);
        const float xc = fminf(fmaxf(x, 0.0f), hv - 1.0f);
        const int x0 = (int)floorf(xc);
        lxv[px] = xc - (float)x0;
        const int xa = x0 & ~3;
        const int xr = x0 - xa;         // 0..3, uniform over the CTA
        xrv[px] = xr;
        t0[px] = *(const float4*)(plane + y0  * 128 + xa);
        t1[px] = *(const float4*)(plane + y1i * 128 + xa);
        if (xr == 3) {
            // x0+1 read stays inside fm; its weight lx is 0 when clamped.
            e0[px] = plane[y0  * 128 + x0 + 1];
            e1[px] = plane[y1i * 128 + x0 + 1];
        } else {
            e0[px] = 0.0f; e1[px] = 0.0f;
        }
    }

    // ---- combine phase ----
    #pragma unroll
    for (int px = 0; px < 3; px++) {
        const int xr = xrv[px];
        const float lx = lxv[px];
        float v00, v01, v10, v11;
        if (xr == 0)      { v00 = t0[px].x; v01 = t0[px].y; v10 = t1[px].x; v11 = t1[px].y; }
        else if (xr == 1) { v00 = t0[px].y; v01 = t0[px].z; v10 = t1[px].y; v11 = t1[px].z; }
        else if (xr == 2) { v00 = t0[px].z; v01 = t0[px].w; v10 = t1[px].z; v11 = t1[px].w; }
        else              { v00 = t0[px].w; v01 = e0[px];   v10 = t1[px].w; v11 = e1[px];   }

        const float val = (1.0f-ly)*(1.0f-lx)*v00 + (1.0f-ly)*lx*v01
                        + ly*(1.0f-lx)*v10 + ly*lx*v11;
        g_R[(size_t)(n * 9 + py * 3 + px) * CCH + c] = vld[px] ? val : 0.0f;
    }
}

// ---------------------------------------------------------------------------
// K2: 3x-BF16 mma.sync GEMM (m16n8k16), fused im2col A-gather, double-buffered.
// grid (9, 2, 8) = 144 CTAs, 256 thr (8 warps 4x2), warp tile 32x64.
// ---------------------------------------------------------------------------
__global__ void __launch_bounds__(256, 1) k_gemm_mma(const float* __restrict__ conv_w)
{
    extern __shared__ uint32_t smu[];   // [2 buf][Ah|Al|Bh|Bl][128*PSTRIDE]

    const int tid  = threadIdx.x;
    const int wid  = tid >> 5;
    const int lane = tid & 31;
    const int warp_m = wid & 3;
    const int warp_n = wid >> 2;

    const int m0 = blockIdx.x * 128;
    const int n0 = blockIdx.y * 128;
    const int k0 = blockIdx.z * KSLICE;

    const int pc   = tid & 15;          // A packed col (constant per thread)
    const int lrow = tid >> 3;          // B gmem row base
    const int lcol = (tid & 7) * 4;     // B gmem k offset (float4)

    float acc[2][8][4];
    #pragma unroll
    for (int i = 0; i < 2; i++)
        #pragma unroll
        for (int j = 0; j < 8; j++)
            #pragma unroll
            for (int q = 0; q < 4; q++) acc[i][j][q] = 0.0f;

    const float* __restrict__ Bbase = conv_w + (size_t)n0 * K_GEMM + k0;

    // A-gather row decode: rows (tid>>4) + i*16, i<8
    int a_n[8], a_py[8], a_px[8];
    #pragma unroll
    for (int i = 0; i < 8; i++) {
        const int row = (tid >> 4) + i * 16;
        const int m = m0 + row;
        const int n = m / 9;
        const int p = m - n * 9;
        a_n[i] = n;
        a_py[i] = p / 3;
        a_px[i] = p - (p / 3) * 3;
    }

    float ra[16];
    float4 rb[4];

    // ---- gather helper (stage kbase) ----
    #define GATHER_A(kbase_)                                                   \
        _Pragma("unroll")                                                      \
        for (int i = 0; i < 8; i++) {                                          \
            _Pragma("unroll")                                                  \
            for (int t = 0; t < 2; t++) {                                      \
                const int k = (kbase_) + pc * 2 + t;                           \
                const int c = k / 9;                                           \
                const int kk = k - c * 9;                                      \
                const int ky = kk / 3, kx = kk - ky * 3;                       \
                const int iy = a_py[i] + ky - 1, ix = a_px[i] + kx - 1;        \
                ra[2*i+t] = ((unsigned)iy < 3u && (unsigned)ix < 3u)           \
                    ? g_R[(size_t)(a_n[i] * 9 + iy * 3 + ix) * CCH + c] : 0.0f;\
            }                                                                  \
        }

    #define STORE_STAGE(bufsel)                                                \
        {                                                                      \
            uint32_t* dAh = smu + (bufsel) * (4 * PTILE);                      \
            uint32_t* dAl = dAh + PTILE;                                       \
            uint32_t* dBh = dAl + PTILE;                                       \
            uint32_t* dBl = dBh + PTILE;                                       \
            _Pragma("unroll")                                                  \
            for (int i = 0; i < 8; i++) {                                      \
                const int row = (tid >> 4) + i * 16;                           \
                const float v0 = ra[2*i], v1 = ra[2*i+1];                      \
                dAh[row * PSTRIDE + pc] = bf2pack(v0, v1);                     \
                dAl[row * PSTRIDE + pc] = bf2pack(v0 - bfhi(v0), v1 - bfhi(v1));\
            }                                                                  \
            _Pragma("unroll")                                                  \
            for (int q = 0; q < 4; q++) {                                      \
                const int row = (tid >> 3) + q * 32;                           \
                const float4 v = rb[q];                                        \
                const int base = row * PSTRIDE + (tid & 7) * 2;                \
                dBh[base]     = bf2pack(v.x, v.y);                             \
                dBh[base + 1] = bf2pack(v.z, v.w);                             \
                dBl[base]     = bf2pack(v.x - bfhi(v.x), v.y - bfhi(v.y));     \
                dBl[base + 1] = bf2pack(v.z - bfhi(v.z), v.w - bfhi(v.w));     \
            }                                                                  \
        }

    // stage 0 prefetch + store
    GATHER_A(k0)
    #pragma unroll
    for (int q = 0; q < 4; q++)
        rb[q] = *(const float4*)(Bbase + (size_t)(lrow + q * 32) * K_GEMM + lcol);
    STORE_STAGE(0)
    __syncthreads();

    for (int s = 0; s < NSTAGE; s++) {
        // issue next-stage gmem loads
        if (s + 1 < NSTAGE) {
            GATHER_A(k0 + (s + 1) * BK)
            #pragma unroll
            for (int q = 0; q < 4; q++)
                rb[q] = *(const float4*)(Bbase + (size_t)(lrow + q * 32) * K_GEMM
                                         + (s + 1) * BK + lcol);
        }

        // compute from buffer s&1
        {
            const uint32_t* sAh = smu + (s & 1) * (4 * PTILE);
            const uint32_t* sAl = sAh + PTILE;
            const uint32_t* sBh = sAl + PTILE;
            const uint32_t* sBl = sBh + PTILE;

            const int rbase = warp_m * 32 + (lane >> 2);
            const int nbase = warp_n * 64 + (lane >> 2);
            #pragma unroll
            for (int kc = 0; kc < 2; kc++) {
                const int kb = kc * 8 + (lane & 3);
                uint32_t ah[2][4], al[2][4];
                #pragma unroll
                for (int i = 0; i < 2; i++) {
                    const int r = rbase + i * 16;
                    ah[i][0] = sAh[r * PSTRIDE + kb];
                    ah[i][1] = sAh[(r + 8) * PSTRIDE + kb];
                    ah[i][2] = sAh[r * PSTRIDE + kb + 4];
                    ah[i][3] = sAh[(r + 8) * PSTRIDE + kb + 4];
                    al[i][0] = sAl[r * PSTRIDE + kb];
                    al[i][1] = sAl[(r + 8) * PSTRIDE + kb];
                    al[i][2] = sAl[r * PSTRIDE + kb + 4];
                    al[i][3] = sAl[(r + 8) * PSTRIDE + kb + 4];
                }
                #pragma unroll
                for (int j = 0; j < 8; j++) {
                    const int nn = nbase + j * 8;
                    const uint32_t bh0 = sBh[nn * PSTRIDE + kb];
                    const uint32_t bh1 = sBh[nn * PSTRIDE + kb + 4];
                    const uint32_t bl0 = sBl[nn * PSTRIDE + kb];
                    const uint32_t bl1 = sBl[nn * PSTRIDE + kb + 4];
                    #pragma unroll
                    for (int i = 0; i < 2; i++) {
                        mma_bf16(acc[i][j], ah[i][0], ah[i][1], ah[i][2], ah[i][3], bh0, bh1);
                        mma_bf16(acc[i][j], ah[i][0], ah[i][1], ah[i][2], ah[i][3], bl0, bl1);
                        mma_bf16(acc[i][j], al[i][0], al[i][1], al[i][2], al[i][3], bh0, bh1);
                    }
                }
            }
        }

        // store next stage into other buffer
        if (s + 1 < NSTAGE) {
            STORE_STAGE((s + 1) & 1)
        }
        __syncthreads();
    }

    float* __restrict__ hp = g_hpart + (size_t)blockIdx.z * ((size_t)M_GEMM * N_GEMM);
    #pragma unroll
    for (int i = 0; i < 2; i++) {
        const int row = m0 + warp_m * 32 + i * 16 + (lane >> 2);
        #pragma unroll
        for (int j = 0; j < 8; j++) {
            const int col = n0 + warp_n * 64 + j * 8 + 2 * (lane & 3);
            *(float2*)(hp + (size_t)row * N_GEMM + col) =
                make_float2(acc[i][j][0], acc[i][j][1]);
            *(float2*)(hp + (size_t)(row + 8) * N_GEMM + col) =
                make_float2(acc[i][j][2], acc[i][j][3]);
        }
    }
}

// ---------------------------------------------------------------------------
// K3: per-roi epilogue with fused split-K reduce. 1024 threads.
// ---------------------------------------------------------------------------
__global__ void __launch_bounds__(1024) k_epilogue(
    const float* __restrict__ boxes,
    const float* __restrict__ gn_scale, const float* __restrict__ gn_bias,
    const float* __restrict__ head_w,   const float* __restrict__ head_b,
    const float* __restrict__ spat_w,   const float* __restrict__ spat_b,
    const float* __restrict__ sym_emb,
    const float* __restrict__ fuse_w,   const float* __restrict__ fuse_b,
    const int*   __restrict__ sym_ids,
    float* __restrict__ out)
{
    const int n   = blockIdx.x;
    const int tid = threadIdx.x;
    const int w   = tid >> 5;
    const int l   = tid & 31;

    __shared__ __align__(16) float hred[9 * 256];
    __shared__ __align__(16) float sbuf[256];
    __shared__ __align__(16) float fbuf[256];
    __shared__ float hobuf[256];

    const int sym = sym_ids[n];

    // ---- Phase 0: split-K reduce (float4, coalesced): 576 float4s ----
    if (tid < 576) {
        const float4* __restrict__ hp4 = (const float4*)g_hpart;
        const size_t stride4 = (size_t)M_GEMM * N_GEMM / 4;
        const size_t base4 = (size_t)(n * 9) * (N_GEMM / 4) + tid;
        float4 s = hp4[base4];
        #pragma unroll
        for (int sp = 1; sp < SPLITK; sp++) {
            const float4 v = hp4[(size_t)sp * stride4 + base4];
            s.x += v.x; s.y += v.y; s.z += v.z; s.w += v.w;
        }
        ((float4*)hred)[tid] = s;
    }
    __syncthreads();

    // ---- Phase 1: GN + relu + spatial mean (threads 0..255; warp == group) ----
    if (tid < 256) {
        const int e = tid;
        float hvp[9];
        #pragma unroll
        for (int p = 0; p < 9; p++)
            hvp[p] = hred[p * 256 + e];

        float lsum = 0.0f;
        #pragma unroll
        for (int p = 0; p < 9; p++) lsum += hvp[p];
        #pragma unroll
        for (int o = 16; o > 0; o >>= 1) lsum += __shfl_xor_sync(0xffffffffu, lsum, o);
        const float mean = lsum * (1.0f / 288.0f);

        float lsq = 0.0f;
        #pragma unroll
        for (int p = 0; p < 9; p++) { float d = hvp[p] - mean; lsq += d * d; }
        #pragma unroll
        for (int o = 16; o > 0; o >>= 1) lsq += __shfl_xor_sync(0xffffffffu, lsq, o);
        const float inv = rsqrtf(lsq * (1.0f / 288.0f) + 1e-5f);

        const float sc = gn_scale[e];
        const float bi = gn_bias[e];
        float acc = 0.0f;
        #pragma unroll
        for (int p = 0; p < 9; p++)
            acc += fmaxf((hvp[p] - mean) * inv * sc + bi, 0.0f);
        sbuf[e] = acc * (1.0f / 9.0f);
    }
    __syncthreads();

    // ---- Phase 2: head GEMV (warp w -> outputs w*8..w*8+7, float4 loads) ----
    {
        const float4 sva = *(const float4*)&sbuf[l * 4];
        const float4 svb = *(const float4*)&sbuf[128 + l * 4];

        float a[8];
        #pragma unroll
        for (int o = 0; o < 8; o++) {
            const float* __restrict__ row = head_w + (size_t)(w * 8 + o) * 256;
            const float4 wa = *(const float4*)(row + l * 4);
            const float4 wb = *(const float4*)(row + 128 + l * 4);
            float t = sva.x * wa.x + sva.y * wa.y + sva.z * wa.z + sva.w * wa.w;
            t = fmaf(svb.x, wb.x, t); t = fmaf(svb.y, wb.y, t);
            t = fmaf(svb.z, wb.z, t); t = fmaf(svb.w, wb.w, t);
            a[o] = t;
        }
        #pragma unroll
        for (int o = 0; o < 8; o++) {
            #pragma unroll
            for (int off = 16; off > 0; off >>= 1)
                a[o] += __shfl_xor_sync(0xffffffffu, a[o], off);
        }
        if (l < 8) {
            const int e = w * 8 + l;
            float v = a[0];
            #pragma unroll
            for (int o = 1; o < 8; o++) v = (l == o) ? a[o] : v;
            hobuf[e] = v + head_b[e];
        }
    }
    __syncthreads();

    // ---- fused vector (threads 0..255) ----
    if (tid < 256) {
        const int e = tid;
        const float ho = fmaxf(hobuf[e], 0.0f);
        const float b0 = boxes[n*4+0], b1 = boxes[n*4+1],
                    b2 = boxes[n*4+2], b3 = boxes[n*4+3];
        float sp = spat_b[e] + b0 * spat_w[e*4+0] + b1 * spat_w[e*4+1]
                             + b2 * spat_w[e*4+2] + b3 * spat_w[e*4+3];
        sp = fmaxf(sp, 0.0f);
        fbuf[e] = ho + sp + sym_emb[sym * 256 + e];
    }
    __syncthreads();

    // ---- Phase 3: fuse GEMV ----
    {
        const float4 fva = *(const float4*)&fbuf[l * 4];
        const float4 fvb = *(const float4*)&fbuf[128 + l * 4];

        float a[8];
        #pragma unroll
        for (int o = 0; o < 8; o++) {
            const float* __restrict__ row =
                fuse_w + ((size_t)sym * 256 + (size_t)(w * 8 + o)) * 256;
            const float4 wa = *(const float4*)(row + l * 4);
            const float4 wb = *(const float4*)(row + 128 + l * 4);
            float t = fva.x * wa.x + fva.y * wa.y + fva.z * wa.z + fva.w * wa.w;
            t = fmaf(fvb.x, wb.x, t); t = fmaf(fvb.y, wb.y, t);
            t = fmaf(fvb.z, wb.z, t); t = fmaf(fvb.w, wb.w, t);
            a[o] = t;
        }
        #pragma unroll
        for (int o = 0; o < 8; o++) {
            #pragma unroll
            for (int off = 16; off > 0; off >>= 1)
                a[o] += __shfl_xor_sync(0xffffffffu, a[o], off);
        }
        if (l < 8) {
            const int e = w * 8 + l;
            float v = a[0];
            #pragma unroll
            for (int o = 1; o < 8; o++) v = (l == o) ? a[o] : v;
            out[(size_t)n * 256 + e] = fmaxf(v + fuse_b[sym * 256 + e], 0.0f);
        }
    }
}

// ---------------------------------------------------------------------------
extern "C" void kernel_launch(void* const* d_in, const int* in_sizes, int n_in,
                              void* d_out, int out_size)
{
    const float* fm        = (const float*)d_in[0];
    const float* boxes     = (const float*)d_in[1];
    const float* conv_w    = (const float*)d_in[2];
    const float* gn_scale  = (const float*)d_in[3];
    const float* gn_bias   = (const float*)d_in[4];
    const float* head_w    = (const float*)d_in[5];
    const float* head_b    = (const float*)d_in[6];
    const float* spat_w    = (const float*)d_in[7];
    const float* spat_b    = (const float*)d_in[8];
    const float* sym_emb   = (const float*)d_in[9];
    const float* fuse_w    = (const float*)d_in[10];
    const float* fuse_b    = (const float*)d_in[11];
    const int*   batch_idx = (const int*)d_in[12];
    const int*   level_idx = (const int*)d_in[13];
    const int*   sym_ids   = (const int*)d_in[14];
    float* out = (float*)d_out;

    cudaFuncSetAttribute(k_gemm_mma,
                         cudaFuncAttributeMaxDynamicSharedMemorySize, GEMM_SMEM_BYTES);

    dim3 g1(NROI, 3);
    k_roi<<<g1, 256>>>(fm, boxes, batch_idx, level_idx);

    dim3 g2(M_GEMM / 128, N_GEMM / 128, SPLITK);   // (9, 2, 8) = 144 CTAs
    k_gemm_mma<<<g2, 256, GEMM_SMEM_BYTES>>>(conv_w);

    k_epilogue<<<NROI, 1024>>>(boxes, gn_scale, gn_bias, head_w, head_b,
                               spat_w, spat_b, sym_emb, fuse_w, fuse_b,
                               sym_ids, out);
}